// round 15
// baseline (speedup 1.0000x reference)
#include <cuda_runtime.h>
#include <cuda_bf16.h>
#include <cstdint>

typedef unsigned int u32; typedef unsigned short u16;

// AttentionMV B=T=1024, E=128. mma.sync bf16 3-pass split. R15.
// t-split: CTA (bb, th) runs R9's engine on t in [th*512, th*512+512) (8 tiles
// of 64t). smem 100KB, regs <=128 -> 2 CTAs/SM (independent barriers ->
// phase-drifted tensor streams). Partial pre/colsum -> gmem; kernel2 reduces.

constexpr int NT = 256;
constexpr u32 WFH=0, WFL=32768;          // W frags 64KB
constexpr u32 MFH=65536, MFL=81920;      // m frags 32KB (single buffer)
constexpr u32 SP_OFF=98304;              // 8*128 f32 colsum partials
constexpr u32 SMEM_BYTES=102400;

__device__ u16 g_vtFH[131072];           // vT A-frag images, 16KB per 64-t tile
__device__ u16 g_vtFL[131072];
__device__ float g_biasF[131072];        // bias packed in accum-frag order
__device__ float g_pre[33554432];        // [2048 ctas][128e][128f]
__device__ float g_s[262144];            // [2048 ctas][128e]

__device__ __forceinline__ float fast_tanh(float x){
    float e = __expf(2.0f*x);
    return 1.0f - __fdividef(2.0f, e+1.0f);
}
__device__ __forceinline__ float trunc_hi(float x){
    return __uint_as_float(__float_as_uint(x) & 0xffff0000u);
}
__device__ __forceinline__ u32 cvt_bf16x2(float hiArg, float loArg){
    u32 d; asm("cvt.rn.bf16x2.f32 %0, %1, %2;" : "=r"(d) : "f"(hiArg), "f"(loArg));
    return d;
}
__device__ __forceinline__ void mma16816(float* d, u32 a0,u32 a1,u32 a2,u32 a3,
                                         u32 b0,u32 b1){
    asm volatile("mma.sync.aligned.m16n8k16.row.col.f32.bf16.bf16.f32 "
        "{%0,%1,%2,%3}, {%4,%5,%6,%7}, {%8,%9}, {%0,%1,%2,%3};"
        : "+f"(d[0]),"+f"(d[1]),"+f"(d[2]),"+f"(d[3])
        : "r"(a0),"r"(a1),"r"(a2),"r"(a3),"r"(b0),"r"(b1));
}

// vT A-frag prep (verified R9 layout, global 64-t tile indexing)
__global__ void vt_prep(const float* __restrict__ gv){
    int t = blockIdx.x, e = threadIdx.x;
    float x = gv[t*128 + e];
    u16 hi = (u16)(__float_as_uint(x) >> 16);
    u16 lo = __bfloat16_as_ushort(__float2bfloat16(x - trunc_hi(x)));
    int tile = t>>6, s = (t>>4)&3, tr = t&15;
    int kh = tr>>3, rs = (tr&7)>>1, byt = tr&1;
    int i = e>>4, eq = e&15, rh = eq>>3, q = eq&7;
    int reg = rh + 2*kh, lane = q*4 + rs;
    int idx = ((tile*32 + i*4 + s)*32 + lane)*8 + reg*2 + byt;
    g_vtFH[idx] = hi; g_vtFL[idx] = lo;
}

// bias packed in accum-frag order (verified R12 mapping)
__global__ void bias_prep(const float* __restrict__ gb){
    int idx = blockIdx.x*256 + threadIdx.x;
    int c = idx&3, nb=(idx>>2)&7, lane=(idx>>5)&31, w=(idx>>10)&7, tile=idx>>13;
    int q=lane>>2, r2=(lane&3)*2;
    int t = tile*64 + nb*8 + r2 + (c&1);
    int f = w*16 + q + 8*(c>>1);
    g_biasF[idx] = gb[t*128+f];
}

__global__ __launch_bounds__(NT,2)
void attn_mma(const float* __restrict__ gm, const float* __restrict__ gW)
{
    extern __shared__ char sm[];
    const int tid=threadIdx.x, lane=tid&31, w=tid>>5;
    const int bb = blockIdx.x>>1, th = blockIdx.x&1;
    const int q=lane>>2, r2=(lane&3)*2;
    const float* Wb = gW + (size_t)bb*16384;
    const float4* mb4 = (const float4*)(gm + (size_t)bb*131072) + (size_t)th*16384;

    const int m_ks = lane>>2, m_r = (lane>>1)&1;
    const int m_l  = w*4 + (lane&1)*2;

    // ---- W -> A-frag layout (verified R9 mapping)
    for (int it=0; it<64; it++){
        int idx = it*NT + tid;
        int e = idx>>7, f = idx&127;
        float x = __ldg(Wb + idx);
        u16 hi = (u16)(__float_as_uint(x) >> 16);
        u16 lo = __bfloat16_as_ushort(__float2bfloat16(x - trunc_hi(x)));
        int w2=f>>4, fr=f&15, rh=fr>>3, qq=fr&7;
        int ks=e>>4, er=e&15, kh=er>>3, rs=(er&7)>>1, byt=er&1;
        u32 off = (u32)(((w2*8+ks)*32 + qq*4 + rs)*16 + (rh + 2*kh)*4 + byt*2);
        *(u16*)(sm + WFH + off) = hi;
        *(u16*)(sm + WFL + off) = lo;
    }

    float s4[4]={0,0,0,0};

    // m-split of 4 rows (j = jp*4..+3), verified R9 layout
    auto msplit4 = [&](const float4* src, int jp){
        float4 xs[4];
        #pragma unroll
        for (int u2=0;u2<4;u2++) xs[u2] = __ldg(src + (jp*4+u2)*256 + tid);
        #pragma unroll
        for (int u2=0;u2<4;u2++){
            int j = jp*4+u2; float4 x = xs[u2];
            s4[0]+=x.x; s4[1]+=x.y; s4[2]+=x.z; s4[3]+=x.w;
            u32 hA = __byte_perm(__float_as_uint(x.x), __float_as_uint(x.y), 0x7632);
            u32 hB = __byte_perm(__float_as_uint(x.z), __float_as_uint(x.w), 0x7632);
            float l0 = x.x - trunc_hi(x.x), l1 = x.y - trunc_hi(x.y);
            float l2 = x.z - trunc_hi(x.z), l3 = x.w - trunc_hi(x.w);
            u32 lA = cvt_bf16x2(l1, l0), lB = cvt_bf16x2(l3, l2);
            u32 blk = (u32)((j*8 + m_ks) << 8);
            u32 iA = (u32)((m_l*2     + m_r + m_ks*8) & 63)*4;
            u32 iB = (u32)(((m_l+1)*2 + m_r + m_ks*8) & 63)*4;
            *(u32*)(sm + MFH + blk + iA) = hA;
            *(u32*)(sm + MFH + blk + iB) = hB;
            *(u32*)(sm + MFL + blk + iA) = lA;
            *(u32*)(sm + MFL + blk + iB) = lB;
        }
    };

    // prologue: frag m(tile 0 of this CTA)
    msplit4(mb4, 0); msplit4(mb4, 1);

    float pre[8][2][4];
    #pragma unroll
    for (int i=0;i<8;i++)
        #pragma unroll
        for (int fb=0;fb<2;fb++)
            #pragma unroll
            for (int j=0;j<4;j++) pre[i][fb][j]=0.f;

    __syncthreads();   // WF + MF(0) visible

    for (int k=0;k<8;k++){
        const int t64 = th*8 + k;

        // ---- GEMM1 (window1): f rows w*16..+15, t cols 0..63, nb-chunks of 4
        float d1[8][4];
        #pragma unroll
        for (int nb=0;nb<8;nb++){ d1[nb][0]=0;d1[nb][1]=0;d1[nb][2]=0;d1[nb][3]=0; }
        #pragma unroll
        for (int ks=0;ks<8;ks++){
            uint4 ahv = *(const uint4*)(sm + WFH + (u32)(((w*8+ks)*32+lane)*16));
            uint4 alv = *(const uint4*)(sm + WFL + (u32)(((w*8+ks)*32+lane)*16));
            u32 bpos = (u32)(((lane*2) + ks*8) & 63)*4;
            #pragma unroll
            for (int nc=0;nc<2;nc++){
                uint2 bh[4], bl[4];
                #pragma unroll
                for (int n4=0;n4<4;n4++){
                    int nb = nc*4+n4;
                    bh[n4] = *(const uint2*)(sm + MFH + (u32)((nb*8+ks)<<8) + bpos);
                    bl[n4] = *(const uint2*)(sm + MFL + (u32)((nb*8+ks)<<8) + bpos);
                }
                #pragma unroll
                for (int n4=0;n4<4;n4++)
                    mma16816(d1[nc*4+n4], ahv.x,ahv.y,ahv.z,ahv.w, bh[n4].x,bh[n4].y);
                #pragma unroll
                for (int n4=0;n4<4;n4++)
                    mma16816(d1[nc*4+n4], ahv.x,ahv.y,ahv.z,ahv.w, bl[n4].x,bl[n4].y);
                #pragma unroll
                for (int n4=0;n4<4;n4++)
                    mma16816(d1[nc*4+n4], alv.x,alv.y,alv.z,alv.w, bh[n4].x,bh[n4].y);
            }
        }

        // ---- bias (frag-packed) + tanh + split, 2 chunks of 4 nb
        u32 uh[8][2], ul[8][2];
        const float4* bfr = (const float4*)g_biasF + ((size_t)(t64*8+w)*32+lane)*8;
        #pragma unroll
        for (int nc=0;nc<2;nc++){
            float4 b4[4];
            #pragma unroll
            for (int n4=0;n4<4;n4++) b4[n4] = __ldg(bfr + nc*4 + n4);
            #pragma unroll
            for (int n4=0;n4<4;n4++){
                int nb = nc*4+n4;
                float u0=fast_tanh(d1[nb][0]+b4[n4].x);
                float u1=fast_tanh(d1[nb][1]+b4[n4].y);
                float u2=fast_tanh(d1[nb][2]+b4[n4].z);
                float u3=fast_tanh(d1[nb][3]+b4[n4].w);
                uh[nb][0] = __byte_perm(__float_as_uint(u0), __float_as_uint(u1), 0x7632);
                uh[nb][1] = __byte_perm(__float_as_uint(u2), __float_as_uint(u3), 0x7632);
                ul[nb][0] = cvt_bf16x2(u1 - trunc_hi(u1), u0 - trunc_hi(u0));
                ul[nb][1] = cvt_bf16x2(u3 - trunc_hi(u3), u2 - trunc_hi(u2));
            }
        }
        __syncthreads();   // syncB: GEMM1's MF reads done

        // ---- window2: frag m(k+1), then GEMM2(k)
        if (k<7){
            const float4* msrc = mb4 + (size_t)(k+1)*2048;
            msplit4(msrc, 0); msplit4(msrc, 1);
        }

        const char* vH = (const char*)g_vtFH;
        const char* vL = (const char*)g_vtFL;
        #pragma unroll
        for (int s=0;s<4;s++){
            #pragma unroll
            for (int ih=0;ih<4;ih++){
                size_t a0 = ((size_t)((t64*32 + (ih*2)*4 + s)*32 + lane))*16;
                size_t a1 = ((size_t)((t64*32 + (ih*2+1)*4 + s)*32 + lane))*16;
                uint4 aH0 = __ldg((const uint4*)(vH + a0));
                uint4 aH1 = __ldg((const uint4*)(vH + a1));
                uint4 aL0 = __ldg((const uint4*)(vL + a0));
                uint4 aL1 = __ldg((const uint4*)(vL + a1));
                int i0 = ih*2, i1 = ih*2+1;
                #pragma unroll
                for (int fb=0;fb<2;fb++){
                    mma16816(pre[i0][fb], aH0.x,aH0.y,aH0.z,aH0.w, uh[2*s][fb], uh[2*s+1][fb]);
                    mma16816(pre[i1][fb], aH1.x,aH1.y,aH1.z,aH1.w, uh[2*s][fb], uh[2*s+1][fb]);
                }
                #pragma unroll
                for (int fb=0;fb<2;fb++){
                    mma16816(pre[i0][fb], aH0.x,aH0.y,aH0.z,aH0.w, ul[2*s][fb], ul[2*s+1][fb]);
                    mma16816(pre[i1][fb], aH1.x,aH1.y,aH1.z,aH1.w, ul[2*s][fb], ul[2*s+1][fb]);
                }
                #pragma unroll
                for (int fb=0;fb<2;fb++){
                    mma16816(pre[i0][fb], aL0.x,aL0.y,aL0.z,aL0.w, uh[2*s][fb], uh[2*s+1][fb]);
                    mma16816(pre[i1][fb], aL1.x,aL1.y,aL1.z,aL1.w, uh[2*s][fb], uh[2*s+1][fb]);
                }
            }
        }
        __syncthreads();   // syncA: MF(k+1) visible for next GEMM1
    }

    // ---- write partial pre + colsum
    float* pb = g_pre + (size_t)blockIdx.x*16384;
    #pragma unroll
    for (int i=0;i<8;i++)
        #pragma unroll
        for (int fb=0;fb<2;fb++){
            int e0 = i*16+q, ff = w*16+fb*8+r2;
            *(float2*)(pb + e0*128 + ff)     = make_float2(pre[i][fb][0], pre[i][fb][1]);
            *(float2*)(pb + (e0+8)*128 + ff) = make_float2(pre[i][fb][2], pre[i][fb][3]);
        }
    float* SP = (float*)(sm + SP_OFF);
    *(float4*)(SP + w*128 + lane*4) = make_float4(s4[0],s4[1],s4[2],s4[3]);
    __syncthreads();
    if (tid < 128){
        float ss = 0;
        #pragma unroll
        for (int ww=0;ww<8;ww++) ss += SP[ww*128+tid];
        g_s[(size_t)blockIdx.x*128 + tid] = ss;
    }
}

// ---- kernel2: reduce halves + softmax + output
constexpr u32 K2_SMEM = 128*132*4 + 512;
__global__ void softmax_out2(float* __restrict__ gout){
    extern __shared__ float sm2[];
    float* EX = sm2;                 // [f*132 + e]
    float* CF = sm2 + 128*132;
    const int tid = threadIdx.x, bb = blockIdx.x;
    const float4* p0 = (const float4*)(g_pre + (size_t)(bb*2)  *16384 + tid*128);
    const float4* p1 = (const float4*)(g_pre + (size_t)(bb*2+1)*16384 + tid*128);
    float4 row[32];
    float mx = -1e30f;
    #pragma unroll 8
    for (int j=0;j<32;j++){
        float4 a = __ldg(p0+j), b = __ldg(p1+j);
        row[j] = make_float4(a.x+b.x, a.y+b.y, a.z+b.z, a.w+b.w);
        mx = fmaxf(mx, fmaxf(fmaxf(row[j].x,row[j].y), fmaxf(row[j].z,row[j].w)));
    }
    float sum = 0.f;
    #pragma unroll 4
    for (int j=0;j<32;j++){
        float e0=__expf(row[j].x-mx), e1=__expf(row[j].y-mx);
        float e2=__expf(row[j].z-mx), e3=__expf(row[j].w-mx);
        sum += (e0+e1)+(e2+e3);
        EX[(j*4+0)*132+tid]=e0; EX[(j*4+1)*132+tid]=e1;
        EX[(j*4+2)*132+tid]=e2; EX[(j*4+3)*132+tid]=e3;
    }
    float ss = g_s[(size_t)(bb*2)*128+tid] + g_s[(size_t)(bb*2+1)*128+tid];
    CF[tid] = ss * __fdividef(1.f, sum);
    __syncthreads();
    float acc = 0;
    #pragma unroll 8
    for (int e=0;e<128;e++) acc = fmaf(CF[e], EX[tid*132+e], acc);
    gout[(size_t)bb*128+tid] = acc;
}

extern "C" void kernel_launch(void* const* d_in, const int* in_sizes, int n_in,
                              void* d_out, int out_size) {
    const float* m = (const float*)d_in[0];
    const float* v = (const float*)d_in[1];
    const float* W = (const float*)d_in[2];
    const float* b = (const float*)d_in[3];
    float* out = (float*)d_out;

    vt_prep<<<1024, 128>>>(v);
    bias_prep<<<512, 256>>>(b);
    cudaFuncSetAttribute(attn_mma, cudaFuncAttributeMaxDynamicSharedMemorySize,
                         (int)SMEM_BYTES);
    attn_mma<<<2048, NT, SMEM_BYTES>>>(m, W);
    cudaFuncSetAttribute(softmax_out2, cudaFuncAttributeMaxDynamicSharedMemorySize,
                         (int)K2_SMEM);
    softmax_out2<<<1024, 128, K2_SMEM>>>(out);
}

// round 16
// speedup vs baseline: 1.4835x; 1.4835x over previous
#include <cuda_runtime.h>
#include <cuda_bf16.h>
#include <cstdint>

typedef unsigned int u32; typedef unsigned short u16;

// AttentionMV B=T=1024, E=128. mma.sync bf16 3-pass split.
// R16 = R9 (best: 700.9us) + ONE change: bias packed in accum-frag order by a
// prep kernel -> 8 coalesced LDG.128 at tile start (was 32 scattered LDGs
// consumed immediately inside the tanh epilogue).
//  GEMM1 (per 64-t tile): D1[f][t] = sum_e WT[f][e]*m[t][e]
//  u = tanh(D1+b) -> bf16 hi/lo in registers (accum layout == B-frag layout)
//  GEMM2: pre[e][f] += sum_t vT[e][t]*u[t][f]  (reg accum over all tiles)

constexpr int NT = 256;
constexpr u32 WFH = 0;          // W frag hi: 64 blk * 512B = 32KB
constexpr u32 WFL = 32768;
constexpr u32 MFH = 65536;      // m frag hi: 64 blk * 256B = 16KB
constexpr u32 MFL = 81920;
constexpr u32 VT0 = 98304;      // vT frag buf0: hi 16KB + lo 16KB
constexpr u32 VT1 = 131072;
constexpr u32 P_OFF  = 0;
constexpr u32 EX_OFF = 98304;
constexpr u32 SP_OFF = 165888;  // 8*128 f32
constexpr u32 CF_OFF = 169984;  // 128 f32
constexpr u32 SMEM_BYTES = 170496;

__device__ u16 g_vtFH[131072];   // vT A-frag images, per tile 16KB
__device__ u16 g_vtFL[131072];
__device__ float g_biasF[131072];  // bias packed in accum-frag order

__device__ __forceinline__ float fast_tanh(float x){
    float e = __expf(2.0f*x);
    return 1.0f - __fdividef(2.0f, e+1.0f);
}
__device__ __forceinline__ float trunc_hi(float x){
    return __uint_as_float(__float_as_uint(x) & 0xffff0000u);
}
__device__ __forceinline__ u32 cvt_bf16x2(float hiArg, float loArg){
    u32 d; asm("cvt.rn.bf16x2.f32 %0, %1, %2;" : "=r"(d) : "f"(hiArg), "f"(loArg));
    return d;
}
__device__ __forceinline__ void mma16816(float* d, u32 a0,u32 a1,u32 a2,u32 a3,
                                         u32 b0,u32 b1){
    asm volatile("mma.sync.aligned.m16n8k16.row.col.f32.bf16.bf16.f32 "
        "{%0,%1,%2,%3}, {%4,%5,%6,%7}, {%8,%9}, {%0,%1,%2,%3};"
        : "+f"(d[0]),"+f"(d[1]),"+f"(d[2]),"+f"(d[3])
        : "r"(a0),"r"(a1),"r"(a2),"r"(a3),"r"(b0),"r"(b1));
}
__device__ __forceinline__ u32 smem_u32(const void* p){
    u32 a; asm("{ .reg .u64 t; cvta.to.shared.u64 t, %1; cvt.u32.u64 %0, t; }"
               : "=r"(a) : "l"(p));
    return a;
}
__device__ __forceinline__ void cp16(u32 dst, const void* src){
    asm volatile("cp.async.ca.shared.global [%0], [%1], 16;" :: "r"(dst), "l"(src));
}

// vT A-frag prep: a-frag for A[m=e][k=t] (verified R9 layout)
__global__ void vt_prep(const float* __restrict__ gv){
    int t = blockIdx.x, e = threadIdx.x;
    float x = gv[t*128 + e];
    u16 hi = (u16)(__float_as_uint(x) >> 16);
    u16 lo = __bfloat16_as_ushort(__float2bfloat16(x - trunc_hi(x)));
    int tile = t>>6, s = (t>>4)&3, tr = t&15;
    int kh = tr>>3, rs = (tr&7)>>1, byt = tr&1;
    int i = e>>4, eq = e&15, rh = eq>>3, q = eq&7;
    int reg = rh + 2*kh, lane = q*4 + rs;
    int idx = ((tile*32 + i*4 + s)*32 + lane)*8 + reg*2 + byt;
    g_vtFH[idx] = hi; g_vtFL[idx] = lo;
}

// bias packed in accumulator-fragment order (verified R12 mapping):
// idx = (((tile*8+w)*32+lane)*8+nb)*4+c -> b[t][f],
// t = tile*64+nb*8+(lane&3)*2+(c&1), f = w*16+(lane>>2)+8*(c>>1)
__global__ void bias_prep(const float* __restrict__ gb){
    int idx = blockIdx.x*256 + threadIdx.x;
    int c = idx&3, nb=(idx>>2)&7, lane=(idx>>5)&31, w=(idx>>10)&7, tile=idx>>13;
    int q=lane>>2, r2=(lane&3)*2;
    int t = tile*64 + nb*8 + r2 + (c&1);
    int f = w*16 + q + 8*(c>>1);
    g_biasF[idx] = gb[t*128+f];
}

__global__ __launch_bounds__(NT,1)
void attn_mma(const float* __restrict__ gm, const float* __restrict__ gW,
              float* __restrict__ gout)
{
    extern __shared__ char sm[];
    const u32 sbase = smem_u32(sm);
    const int tid=threadIdx.x, lane=tid&31, w=tid>>5, bb=blockIdx.x;
    const int q=lane>>2, r2=(lane&3)*2;
    const float* Wb = gW + (size_t)bb*16384;
    const float4* mb4 = (const float4*)(gm + (size_t)bb*131072);

    // ---- W -> A-frag layout
    for (int it=0; it<64; it++){
        int idx = it*NT + tid;
        int e = idx>>7, f = idx&127;
        float x = __ldg(Wb + idx);
        u16 hi = (u16)(__float_as_uint(x) >> 16);
        u16 lo = __bfloat16_as_ushort(__float2bfloat16(x - trunc_hi(x)));
        int w2=f>>4, fr=f&15, rh=fr>>3, qq=fr&7;
        int ks=e>>4, er=e&15, kh=er>>3, rs=(er&7)>>1, byt=er&1;
        u32 off = (u32)(((w2*8+ks)*32 + qq*4 + rs)*16 + (rh + 2*kh)*4 + byt*2);
        *(u16*)(sm + WFH + off) = hi;
        *(u16*)(sm + WFL + off) = lo;
    }

    // prologue: cp vT(0), load m tile0
    {
        const char* srcH = (const char*)g_vtFH;
        const char* srcL = (const char*)g_vtFL;
        #pragma unroll
        for (int k2=0;k2<4;k2++){
            cp16(sbase + VT0 + tid*64 + k2*16,         srcH + tid*64 + k2*16);
            cp16(sbase + VT0 + 16384 + tid*64 + k2*16, srcL + tid*64 + k2*16);
        }
        asm volatile("cp.async.commit_group;");
    }
    float4 mreg[8];
    #pragma unroll
    for (int j=0;j<8;j++) mreg[j] = __ldg(mb4 + j*NT + tid);

    float pre[8][2][4];
    #pragma unroll
    for (int i=0;i<8;i++)
        #pragma unroll
        for (int fb=0;fb<2;fb++)
            #pragma unroll
            for (int j2=0;j2<4;j2++) pre[i][fb][j2]=0.f;
    float s4[4]={0,0,0,0};

    const int m_ks = lane>>2, m_r = (lane>>1)&1, m_lsub = (lane&1)*2;
    const float4* bfr = (const float4*)g_biasF;

    for (int tile=0; tile<16; tile++){
        const u32 VTp = (tile&1) ? VT1 : VT0;

        // ---- bias prefetch: 8 coalesced LDG.128, consumed after GEMM1
        float4 bl4[8];
        #pragma unroll
        for (int nb=0;nb<8;nb++)
            bl4[nb] = __ldg(bfr + ((size_t)(tile*8+w)*32+lane)*8 + nb);

        // ---- m split -> B-frag layout + colsum
        #pragma unroll
        for (int j=0;j<8;j++){
            float4 x = mreg[j];
            s4[0]+=x.x; s4[1]+=x.y; s4[2]+=x.z; s4[3]+=x.w;
            u32 hA = __byte_perm(__float_as_uint(x.x), __float_as_uint(x.y), 0x7632);
            u32 hB = __byte_perm(__float_as_uint(x.z), __float_as_uint(x.w), 0x7632);
            float l0 = x.x - trunc_hi(x.x), l1 = x.y - trunc_hi(x.y);
            float l2 = x.z - trunc_hi(x.z), l3 = x.w - trunc_hi(x.w);
            u32 lA = cvt_bf16x2(l1, l0), lB = cvt_bf16x2(l3, l2);
            int l  = w*4 + m_lsub;
            u32 base = (u32)((j*8 + m_ks) << 8);
            u32 pA = (u32)((l*2     + m_r + m_ks*8) & 63)*4;
            u32 pB = (u32)(((l+1)*2 + m_r + m_ks*8) & 63)*4;
            *(u32*)(sm + MFH + base + pA) = hA;
            *(u32*)(sm + MFH + base + pB) = hB;
            *(u32*)(sm + MFL + base + pA) = lA;
            *(u32*)(sm + MFL + base + pB) = lB;
        }
        if (tile<15){
            #pragma unroll
            for (int j=0;j<8;j++) mreg[j] = __ldg(mb4 + (tile+1)*2048 + j*NT + tid);
        }
        __syncthreads();                 // A: m frags ready; prev GEMM2 done

        // cp vT(tile+1)
        if (tile<15){
            const u32 VTn = (tile&1) ? VT0 : VT1;
            const char* srcH = (const char*)g_vtFH + (tile+1)*16384;
            const char* srcL = (const char*)g_vtFL + (tile+1)*16384;
            #pragma unroll
            for (int k2=0;k2<4;k2++){
                cp16(sbase + VTn + tid*64 + k2*16,         srcH + tid*64 + k2*16);
                cp16(sbase + VTn + 16384 + tid*64 + k2*16, srcL + tid*64 + k2*16);
            }
        }
        asm volatile("cp.async.commit_group;");

        // ---- GEMM1: warp w -> f rows w*16..+15, t cols 0..63
        float d1[8][4];
        #pragma unroll
        for (int nb=0;nb<8;nb++){ d1[nb][0]=0;d1[nb][1]=0;d1[nb][2]=0;d1[nb][3]=0; }
        #pragma unroll
        for (int ks=0;ks<8;ks++){
            uint4 ahv = *(const uint4*)(sm + WFH + (u32)(((w*8+ks)*32+lane)*16));
            uint4 alv = *(const uint4*)(sm + WFL + (u32)(((w*8+ks)*32+lane)*16));
            u32 bh[8][2], bl[8][2];
            u32 bpos = (u32)(((lane*2) + ks*8) & 63)*4;
            #pragma unroll
            for (int nb=0;nb<8;nb++){
                uint2 t2 = *(const uint2*)(sm + MFH + (u32)((nb*8+ks)<<8) + bpos);
                bh[nb][0]=t2.x; bh[nb][1]=t2.y;
                uint2 t3 = *(const uint2*)(sm + MFL + (u32)((nb*8+ks)<<8) + bpos);
                bl[nb][0]=t3.x; bl[nb][1]=t3.y;
            }
            #pragma unroll
            for (int nb=0;nb<8;nb++)
                mma16816(d1[nb], ahv.x,ahv.y,ahv.z,ahv.w, bh[nb][0],bh[nb][1]);
            #pragma unroll
            for (int nb=0;nb<8;nb++)
                mma16816(d1[nb], ahv.x,ahv.y,ahv.z,ahv.w, bl[nb][0],bl[nb][1]);
            #pragma unroll
            for (int nb=0;nb<8;nb++)
                mma16816(d1[nb], alv.x,alv.y,alv.z,alv.w, bh[nb][0],bh[nb][1]);
        }

        // ---- bias (prefetched regs) + tanh + split (registers only)
        u32 uh[8][2], ul[8][2];
        #pragma unroll
        for (int nb=0;nb<8;nb++){
            float u0=fast_tanh(d1[nb][0]+bl4[nb].x);
            float u1=fast_tanh(d1[nb][1]+bl4[nb].y);
            float u2=fast_tanh(d1[nb][2]+bl4[nb].z);
            float u3=fast_tanh(d1[nb][3]+bl4[nb].w);
            uh[nb][0] = __byte_perm(__float_as_uint(u0), __float_as_uint(u1), 0x7632);
            uh[nb][1] = __byte_perm(__float_as_uint(u2), __float_as_uint(u3), 0x7632);
            ul[nb][0] = cvt_bf16x2(u1 - trunc_hi(u1), u0 - trunc_hi(u0));
            ul[nb][1] = cvt_bf16x2(u3 - trunc_hi(u3), u2 - trunc_hi(u2));
        }

        asm volatile("cp.async.wait_group 1;");
        __syncthreads();                 // B: vT(tile) visible; GEMM1 reads done

        // ---- GEMM2: pass-major, i-quads
        #pragma unroll
        for (int s=0;s<4;s++){
            #pragma unroll
            for (int iq=0;iq<2;iq++){
                u32 ah[4][4], al[4][4];
                #pragma unroll
                for (int ii=0;ii<4;ii++){
                    int i = iq*4+ii;
                    uint4 a4 = *(const uint4*)(sm + VTp + (u32)(((i*4+s)*32+lane)*16));
                    ah[ii][0]=a4.x; ah[ii][1]=a4.y; ah[ii][2]=a4.z; ah[ii][3]=a4.w;
                    uint4 a5 = *(const uint4*)(sm + VTp + 16384 + (u32)(((i*4+s)*32+lane)*16));
                    al[ii][0]=a5.x; al[ii][1]=a5.y; al[ii][2]=a5.z; al[ii][3]=a5.w;
                }
                #pragma unroll
                for (int ii=0;ii<4;ii++)
                    #pragma unroll
                    for (int fb=0;fb<2;fb++)
                        mma16816(pre[iq*4+ii][fb], ah[ii][0],ah[ii][1],ah[ii][2],ah[ii][3],
                                 uh[2*s][fb], uh[2*s+1][fb]);
                #pragma unroll
                for (int ii=0;ii<4;ii++)
                    #pragma unroll
                    for (int fb=0;fb<2;fb++)
                        mma16816(pre[iq*4+ii][fb], ah[ii][0],ah[ii][1],ah[ii][2],ah[ii][3],
                                 ul[2*s][fb], ul[2*s+1][fb]);
                #pragma unroll
                for (int ii=0;ii<4;ii++)
                    #pragma unroll
                    for (int fb=0;fb<2;fb++)
                        mma16816(pre[iq*4+ii][fb], al[ii][0],al[ii][1],al[ii][2],al[ii][3],
                                 uh[2*s][fb], uh[2*s+1][fb]);
            }
        }
    }
    __syncthreads();

    // ---- epilogue
    float* P = (float*)(sm + P_OFF);
    #pragma unroll
    for (int i=0;i<8;i++)
        #pragma unroll
        for (int fb=0;fb<2;fb++){
            int e0 = i*16+q, f0 = w*16+fb*8+r2;
            P[e0*132+f0]       = pre[i][fb][0];
            P[e0*132+f0+1]     = pre[i][fb][1];
            P[(e0+8)*132+f0]   = pre[i][fb][2];
            P[(e0+8)*132+f0+1] = pre[i][fb][3];
        }
    float* SP=(float*)(sm+SP_OFF);
    *(float4*)(SP + w*128 + lane*4) = make_float4(s4[0],s4[1],s4[2],s4[3]);
    __syncthreads();

    float* EX=(float*)(sm+EX_OFF);
    float* CF=(float*)(sm+CF_OFF);
    if (tid<128){
        int e=tid;
        float ss=0;
        #pragma unroll
        for (int ww=0;ww<8;ww++) ss+=SP[ww*128+e];
        float mx=-1e30f;
        #pragma unroll 8
        for (int f=0;f<128;f++) mx=fmaxf(mx,P[e*132+f]);
        float sum=0;
        #pragma unroll 4
        for (int f=0;f<128;f++){
            float ex=__expf(P[e*132+f]-mx);
            sum+=ex; EX[f*132+e]=ex;
        }
        CF[e]=ss*__fdividef(1.f,sum);
    }
    __syncthreads();
    if (tid<128){
        int f=tid; float acc=0;
        #pragma unroll 8
        for (int e=0;e<128;e++) acc=fmaf(CF[e],EX[f*132+e],acc);
        gout[(size_t)bb*128+f]=acc;
    }
}

extern "C" void kernel_launch(void* const* d_in, const int* in_sizes, int n_in,
                              void* d_out, int out_size) {
    const float* m = (const float*)d_in[0];
    const float* v = (const float*)d_in[1];
    const float* W = (const float*)d_in[2];
    const float* b = (const float*)d_in[3];
    float* out = (float*)d_out;

    vt_prep<<<1024, 128>>>(v);
    bias_prep<<<512, 256>>>(b);
    cudaFuncSetAttribute(attn_mma, cudaFuncAttributeMaxDynamicSharedMemorySize,
                         (int)SMEM_BYTES);
    attn_mma<<<1024, NT, SMEM_BYTES>>>(m, W, out);
}